// round 3
// baseline (speedup 1.0000x reference)
#include <cuda_runtime.h>
#include <math.h>

// B=32, T=1024, C=1024, J=2C=2048
// Per step t:
//   a = [h ; x_t] @ Wa^T + ba ; y = gelu_exact(a)
//   y2 = y @ Wb^T + bb
//   h = LN(y2)*gamma + beta + y2 ; out[:,t,:] = h
//
// ONE persistent kernel (128 blocks x 256 thr), grid barriers between phases.
// fp32 throughout. Scratch in __device__ globals (allocation-free rule).

#define BB 32
#define CC 1024
#define TT 1024
#define JD 2048
#define NBLK 128

__device__ __align__(16) float g_h[BB * CC];            // h[b][c]
__device__ __align__(16) float g_ypart[8][JD * BB];     // GEMM1 partials [kc][j][b]
__device__ __align__(16) float g_y2part[16][BB * CC];   // GEMM2 partials [kc][b][n]

// ---- grid barrier (all 128 blocks co-resident) ----
__device__ unsigned g_count = 0;
__device__ volatile unsigned g_gen = 0;

__device__ __forceinline__ void gbar() {
    __syncthreads();
    if (threadIdx.x == 0) {
        __threadfence();
        unsigned gen = g_gen;
        if (atomicAdd(&g_count, 1u) == NBLK - 1u) {
            atomicExch(&g_count, 0u);
            __threadfence();
            g_gen = gen + 1u;
        } else {
            while (g_gen == gen) __nanosleep(32);
        }
        __threadfence();
    }
    __syncthreads();
}

// smem layout (floats):
//  phase A: zs[32][260] (0..8319) | ws[2][128][36] (8320..17535)
//  phase C: zs2[32][132] (0..4223) | ws[2][128][36] (8320..17535)
#define WS_OFF 8320
#define WS_STRIDE (128 * 36)
#define SMEM_FLOATS (WS_OFF + 2 * WS_STRIDE)

__global__ void __launch_bounds__(256, 1)
k_main(const float* __restrict__ x, const float* __restrict__ Wa,
       const float* __restrict__ ba, const float* __restrict__ Wb,
       const float* __restrict__ bb, const float* __restrict__ gamma,
       const float* __restrict__ beta, float* __restrict__ out) {
    extern __shared__ float sm[];
    const int bid = blockIdx.x, tid = threadIdx.x;
    const int tx = tid & 7, ty = tid >> 3;       // tx: b-groups, ty: j/n-groups

    // init h = 0
    for (int i = bid * 256 + tid; i < BB * CC; i += NBLK * 256) g_h[i] = 0.0f;
    gbar();

    for (int t = 0; t < TT; t++) {
        // ================= Phase A: GEMM1 partial =================
        // 16 jt (128-wide j tiles) x 8 kc (256-wide K chunks; kc<4 -> h, else x)
        {
            const int jt = bid & 15, kc = bid >> 4;
            float* zs = sm;                      // [32][260]
            // load z chunk: 256 c x 32 b, stored zs[b][c_local]
            if (kc < 4) {
                const float* hp = g_h + kc * 256;
                for (int i = tid; i < 32 * 64; i += 256) {
                    int b = i >> 6, c4 = (i & 63) * 4;
                    float4 v = __ldcg((const float4*)(hp + b * CC + c4));
                    *(float4*)&zs[b * 260 + c4] = v;
                }
            } else {
                const float* xp = x + (size_t)(kc - 4) * 256 + (size_t)t * CC;
                for (int i = tid; i < 32 * 64; i += 256) {
                    int b = i >> 6, c4 = (i & 63) * 4;
                    float4 v = *(const float4*)(xp + (size_t)b * TT * CC + c4);
                    *(float4*)&zs[b * 260 + c4] = v;
                }
            }
            // weights: row-major ws[j][k], 32-k stages, double buffered
            const float* wrow = Wa + (size_t)(jt * 128) * 2048 + kc * 256;
#pragma unroll
            for (int p = 0; p < 4; p++) {
                int f = tid + p * 256, j = f >> 3, k4 = (f & 7) * 4;
                *(float4*)&sm[WS_OFF + j * 36 + k4] =
                    *(const float4*)(wrow + (size_t)j * 2048 + k4);
            }
            __syncthreads();

            float acc[4][4];
#pragma unroll
            for (int a = 0; a < 4; a++)
#pragma unroll
                for (int b = 0; b < 4; b++) acc[a][b] = 0.0f;

            int buf = 0;
#pragma unroll 1
            for (int ks = 0; ks < 8; ks++) {
                float4 pf[4];
                if (ks < 7) {
#pragma unroll
                    for (int p = 0; p < 4; p++) {
                        int f = tid + p * 256, j = f >> 3, k4 = (f & 7) * 4;
                        pf[p] = *(const float4*)(wrow + (size_t)j * 2048 +
                                                 (ks + 1) * 32 + k4);
                    }
                }
                const float* wc = sm + WS_OFF + buf * WS_STRIDE;
#pragma unroll
                for (int kk = 0; kk < 8; kk++) {
                    float4 wr[4], zr[4];
#pragma unroll
                    for (int jj = 0; jj < 4; jj++)
                        wr[jj] = *(const float4*)&wc[(ty + 32 * jj) * 36 + kk * 4];
#pragma unroll
                    for (int bb2 = 0; bb2 < 4; bb2++)
                        zr[bb2] = *(const float4*)&zs[(tx + 8 * bb2) * 260 +
                                                      ks * 32 + kk * 4];
#pragma unroll
                    for (int jj = 0; jj < 4; jj++)
#pragma unroll
                        for (int bb2 = 0; bb2 < 4; bb2++) {
                            acc[jj][bb2] += wr[jj].x * zr[bb2].x;
                            acc[jj][bb2] += wr[jj].y * zr[bb2].y;
                            acc[jj][bb2] += wr[jj].z * zr[bb2].z;
                            acc[jj][bb2] += wr[jj].w * zr[bb2].w;
                        }
                }
                if (ks < 7) {
                    float* wn = sm + WS_OFF + (buf ^ 1) * WS_STRIDE;
#pragma unroll
                    for (int p = 0; p < 4; p++) {
                        int f = tid + p * 256, j = f >> 3, k4 = (f & 7) * 4;
                        *(float4*)&wn[j * 36 + k4] = pf[p];
                    }
                }
                __syncthreads();
                buf ^= 1;
            }
#pragma unroll
            for (int jj = 0; jj < 4; jj++)
#pragma unroll
                for (int bb2 = 0; bb2 < 4; bb2++) {
                    int j = jt * 128 + ty + 32 * jj, b = tx + 8 * bb2;
                    g_ypart[kc][j * 32 + b] = acc[jj][bb2];
                }
        }
        gbar();

        // ================= Phase C: reduce+bias+gelu fused, GEMM2 partial =====
        // 8 nt (128-wide n tiles) x 16 kc2 (128-wide j chunks)
        {
            const int nt = bid & 7, kc2 = bid >> 3;
            const int j0g = kc2 * 128;
            float* zs2 = sm;                     // [32][132]
            for (int i = tid; i < 32 * 128; i += 256) {
                int b = i & 31, jl = i >> 5;
                float v = ba[j0g + jl];
#pragma unroll
                for (int p = 0; p < 8; p++)
                    v += __ldcg(&g_ypart[p][(j0g + jl) * 32 + b]);
                v = 0.5f * v * (1.0f + erff(v * 0.70710678118654752440f));
                zs2[b * 132 + jl] = v;
            }
            const float* wrow = Wb + (size_t)(nt * 128) * 2048 + j0g;
#pragma unroll
            for (int p = 0; p < 4; p++) {
                int f = tid + p * 256, j = f >> 3, k4 = (f & 7) * 4;
                *(float4*)&sm[WS_OFF + j * 36 + k4] =
                    *(const float4*)(wrow + (size_t)j * 2048 + k4);
            }
            __syncthreads();

            float acc[4][4];
#pragma unroll
            for (int a = 0; a < 4; a++)
#pragma unroll
                for (int b = 0; b < 4; b++) acc[a][b] = 0.0f;

            int buf = 0;
#pragma unroll 1
            for (int ks = 0; ks < 4; ks++) {
                float4 pf[4];
                if (ks < 3) {
#pragma unroll
                    for (int p = 0; p < 4; p++) {
                        int f = tid + p * 256, j = f >> 3, k4 = (f & 7) * 4;
                        pf[p] = *(const float4*)(wrow + (size_t)j * 2048 +
                                                 (ks + 1) * 32 + k4);
                    }
                }
                const float* wc = sm + WS_OFF + buf * WS_STRIDE;
#pragma unroll
                for (int kk = 0; kk < 8; kk++) {
                    float4 wr[4], zr[4];
#pragma unroll
                    for (int nn = 0; nn < 4; nn++)
                        wr[nn] = *(const float4*)&wc[(ty + 32 * nn) * 36 + kk * 4];
#pragma unroll
                    for (int bb2 = 0; bb2 < 4; bb2++)
                        zr[bb2] = *(const float4*)&zs2[(tx + 8 * bb2) * 132 +
                                                       ks * 32 + kk * 4];
#pragma unroll
                    for (int nn = 0; nn < 4; nn++)
#pragma unroll
                        for (int bb2 = 0; bb2 < 4; bb2++) {
                            acc[nn][bb2] += wr[nn].x * zr[bb2].x;
                            acc[nn][bb2] += wr[nn].y * zr[bb2].y;
                            acc[nn][bb2] += wr[nn].z * zr[bb2].z;
                            acc[nn][bb2] += wr[nn].w * zr[bb2].w;
                        }
                }
                if (ks < 3) {
                    float* wn = sm + WS_OFF + (buf ^ 1) * WS_STRIDE;
#pragma unroll
                    for (int p = 0; p < 4; p++) {
                        int f = tid + p * 256, j = f >> 3, k4 = (f & 7) * 4;
                        *(float4*)&wn[j * 36 + k4] = pf[p];
                    }
                }
                __syncthreads();
                buf ^= 1;
            }
#pragma unroll
            for (int nn = 0; nn < 4; nn++)
#pragma unroll
                for (int bb2 = 0; bb2 < 4; bb2++) {
                    int n = nt * 128 + ty + 32 * nn, b = tx + 8 * bb2;
                    g_y2part[kc2][b * 1024 + n] = acc[nn][bb2];
                }
        }
        gbar();

        // ================= Phase D: reduce + bias + LN + residual + out ======
        if (bid < BB) {
            const int b = bid;
            __shared__ float red[8];
            __shared__ float sh2[2];
            const int n4 = tid * 4;
            float4 s = *(const float4*)(bb + n4);
#pragma unroll
            for (int kc = 0; kc < 16; kc++) {
                float4 p = __ldcg((const float4*)&g_y2part[kc][b * 1024 + n4]);
                s.x += p.x; s.y += p.y; s.z += p.z; s.w += p.w;
            }
            // mean
            float ls = s.x + s.y + s.z + s.w;
            for (int o = 16; o; o >>= 1) ls += __shfl_xor_sync(~0u, ls, o);
            if ((tid & 31) == 0) red[tid >> 5] = ls;
            __syncthreads();
            if (tid == 0) {
                float tot = 0;
#pragma unroll
                for (int w = 0; w < 8; w++) tot += red[w];
                sh2[0] = tot * (1.0f / 1024.0f);
            }
            __syncthreads();
            const float mu = sh2[0];
            float d0 = s.x - mu, d1 = s.y - mu, d2 = s.z - mu, d3 = s.w - mu;
            float ls2 = d0 * d0 + d1 * d1 + d2 * d2 + d3 * d3;
            for (int o = 16; o; o >>= 1) ls2 += __shfl_xor_sync(~0u, ls2, o);
            if ((tid & 31) == 0) red[tid >> 5] = ls2;
            __syncthreads();
            if (tid == 0) {
                float tot = 0;
#pragma unroll
                for (int w = 0; w < 8; w++) tot += red[w];
                sh2[1] = rsqrtf(tot * (1.0f / 1024.0f) + 1e-5f);
            }
            __syncthreads();
            const float rs = sh2[1];
            float4 g4 = *(const float4*)(gamma + n4);
            float4 be4 = *(const float4*)(beta + n4);
            float4 hv;
            hv.x = d0 * rs * g4.x + be4.x + s.x;
            hv.y = d1 * rs * g4.y + be4.y + s.y;
            hv.z = d2 * rs * g4.z + be4.z + s.z;
            hv.w = d3 * rs * g4.w + be4.w + s.w;
            *(float4*)&g_h[b * CC + n4] = hv;
            *(float4*)(out + ((size_t)b * TT + t) * CC + n4) = hv;
        }
        gbar();
    }
}

extern "C" void kernel_launch(void* const* d_in, const int* in_sizes, int n_in,
                              void* d_out, int out_size) {
    const float* x     = (const float*)d_in[0];
    const float* Wa    = (const float*)d_in[1];
    const float* ba    = (const float*)d_in[2];
    const float* Wb    = (const float*)d_in[3];
    const float* bb    = (const float*)d_in[4];
    const float* gamma = (const float*)d_in[5];
    const float* beta  = (const float*)d_in[6];
    float* out = (float*)d_out;

    const int smem = SMEM_FLOATS * 4;   // 70144 B
    cudaFuncSetAttribute(k_main, cudaFuncAttributeMaxDynamicSharedMemorySize, smem);
    k_main<<<NBLK, 256, smem>>>(x, Wa, ba, Wb, bb, gamma, beta, out);
}